// round 16
// baseline (speedup 1.0000x reference)
#include <cuda_runtime.h>
#include <cuda_bf16.h>
#include <math.h>
#include <stdint.h>

#define NN   200000
#define MM   12
#define FF   64
#define NBR  41
#define ORIG 92
#define BB   2000
#define SHH  9
#define NC   3
#define HF   128
#define NM   (NN*MM)
#define NPB  (NN/BB)      // 100 atoms per crystal
#define APB  128          // atoms per conv/embed block
// embed smem layout (floats, inside shared dsm)
#define ASTR    100
#define EMB_AS  (APB*ASTR)
#define EMB_SW  (EMB_AS + ORIG*FF)
// edge kernel geometry (mma.sync, 256-edge blocks)
#define EPB   256
#define ETHR  256
#define EBLK  9375        // NM/EPB
#define KSTR  56          // bf16 row stride (112 B)
#define OFF_AH   0
#define OFF_AL   28672
#define OFF_B    57344
#define OFF_B1   89600    // 291 contiguous floats: b1[144], w2[144], b2[3]
#define E_SMEM   90768
#define BTILE    5376
// folded: c0 * alpha * (1/M)
#define WSCALE (0.28209479177387814f * 0.125f / 12.0f)

typedef unsigned long long ull;

// scratch (allocation-free rule: __device__ globals)
__device__ float g_x[(size_t)NN * FF];
__device__ float g_y[(size_t)NN * FF];
__device__ float g_w[(size_t)NC * NM];
// prepacked edge-MLP weights (written by prep_kernel each launch)
__device__ __align__(16) __nv_bfloat16 g_w1pack[6 * 48 * KSTR];  // 32256 B
__device__ float g_aux[291];   // b1[3][48] | w2[3][48] | b2[3]

__device__ __forceinline__ float softplusf(float t) {
    return fmaxf(t, 0.0f) + __logf(1.0f + __expf(-fabsf(t)));
}

__device__ __forceinline__ ull pack2(float lo, float hi) {
    ull r; asm("mov.b64 %0, {%1, %2};" : "=l"(r) : "f"(lo), "f"(hi)); return r;
}
__device__ __forceinline__ void unpack2(ull v, float& lo, float& hi) {
    asm("mov.b64 {%0, %1}, %2;" : "=f"(lo), "=f"(hi) : "l"(v));
}
__device__ __forceinline__ ull fma2(ull a, ull b, ull c) {
    ull d; asm("fma.rn.f32x2 %0, %1, %2, %3;" : "=l"(d) : "l"(a), "l"(b), "l"(c));
    return d;
}
__device__ __forceinline__ uint32_t smem_u32(const void* p) {
    uint32_t a;
    asm("{ .reg .u64 t; cvta.to.shared.u64 t, %1; cvt.u32.u64 %0, t; }" : "=r"(a) : "l"(p));
    return a;
}
__device__ __forceinline__ void mma16816(float* d, const uint32_t* a,
                                         uint32_t b0, uint32_t b1) {
    asm volatile(
        "mma.sync.aligned.m16n8k16.row.col.f32.bf16.bf16.f32 "
        "{%0,%1,%2,%3}, {%4,%5,%6,%7}, {%8,%9}, {%0,%1,%2,%3};"
        : "+f"(d[0]), "+f"(d[1]), "+f"(d[2]), "+f"(d[3])
        : "r"(a[0]), "r"(a[1]), "r"(a[2]), "r"(a[3]), "r"(b0), "r"(b1));
}
__device__ __forceinline__ void ldmat4(uint32_t* a, uint32_t addr) {
    asm volatile("ldmatrix.sync.aligned.m8n8.x4.shared.b16 {%0,%1,%2,%3}, [%4];"
                 : "=r"(a[0]), "=r"(a[1]), "=r"(a[2]), "=r"(a[3]) : "r"(addr));
}

// ---------------------------------------------------------------------------
// 0) prep: pack W1 bf16 split tiles + aux. 2 blocks per launch (3 launches).
// ---------------------------------------------------------------------------
__global__ __launch_bounds__(256) void prep_kernel(
    const float* __restrict__ Wr1, const float* __restrict__ br1,
    const float* __restrict__ Wr2, const float* __restrict__ br2, int bofs)
{
    int b = bofs + blockIdx.x, t = threadIdx.x;
    int lay = b >> 1, split = b & 1;
    for (int i = t; i < 48 * KSTR; i += 256) {
        int r = i / KSTR, k = i - r * KSTR;
        float v = (r < NBR && k < NBR) ? __ldg(&Wr1[lay * NBR * NBR + k * NBR + r]) : 0.f;
        __nv_bfloat16 hb = __float2bfloat16(v);
        g_w1pack[b * 48 * KSTR + i] =
            split ? __float2bfloat16(v - __bfloat162float(hb)) : hb;
    }
    if (b == 0) {
        if (t < 144) {
            int l2 = t / 48, j = t - l2 * 48;
            g_aux[t] = (j < NBR) ? __ldg(&br1[l2 * NBR + j]) : 0.f;
        } else if (t < 288) {
            int q = t - 144; int l2 = q / 48, j = q - l2 * 48;
            g_aux[t] = (j < NBR) ? __ldg(&Wr2[((size_t)l2 * NBR + j) * SHH]) : 0.f;
        } else if (t < 291) {
            g_aux[t] = __ldg(&br2[(t - 288) * SHH]);
        }
    }
}

// ---------------------------------------------------------------------------
// Embed body (R11/R14 structure) — one block = 128 atoms
// ---------------------------------------------------------------------------
__device__ __forceinline__ void embed_body(
    char* dsm, int blk,
    const float* __restrict__ af, const float* __restrict__ W,
    const float* __restrict__ b)
{
    float* a_s = (float*)dsm;
    float* sW  = a_s + EMB_AS;
    float* sb  = a_s + EMB_SW;

    int t = threadIdx.x;
    for (int i = t; i < ORIG * FF; i += 256) sW[i] = __ldg(&W[i]);
    if (t < FF) sb[t] = __ldg(&b[t]);

    int base = blk * APB;

    for (int idx = t; idx < APB * ORIG; idx += 256) {
        int row = idx / ORIG, col = idx - row * ORIG;
        int a = base + row;
        a_s[row * ASTR + col] = (a < NN) ? __ldg(&af[(size_t)a * ORIG + col]) : 0.f;
    }
    __syncthreads();

    int la0 = (t >> 3) * 4;
    int f0  = (t & 7) * 8;
    ull acc[4][4];
    {
        ull b0 = pack2(sb[f0],     sb[f0 + 1]);
        ull b1 = pack2(sb[f0 + 2], sb[f0 + 3]);
        ull b2 = pack2(sb[f0 + 4], sb[f0 + 5]);
        ull b3 = pack2(sb[f0 + 6], sb[f0 + 7]);
        #pragma unroll
        for (int i = 0; i < 4; i++) {
            acc[i][0] = b0; acc[i][1] = b1; acc[i][2] = b2; acc[i][3] = b3;
        }
    }

    #pragma unroll 4
    for (int k4 = 0; k4 < ORIG / 4; k4++) {
        float4 yv[4];
        #pragma unroll
        for (int i = 0; i < 4; i++)
            yv[i] = *(const float4*)&a_s[(la0 + i) * ASTR + k4 * 4];
        #pragma unroll
        for (int c = 0; c < 4; c++) {
            int k = k4 * 4 + c;
            ulonglong2 wa = *(const ulonglong2*)&sW[k * FF + f0];
            ulonglong2 wb = *(const ulonglong2*)&sW[k * FF + f0 + 4];
            #pragma unroll
            for (int i = 0; i < 4; i++) {
                float yc = (c == 0) ? yv[i].x : (c == 1) ? yv[i].y : (c == 2) ? yv[i].z : yv[i].w;
                ull y2 = pack2(yc, yc);
                acc[i][0] = fma2(y2, wa.x, acc[i][0]);
                acc[i][1] = fma2(y2, wa.y, acc[i][1]);
                acc[i][2] = fma2(y2, wb.x, acc[i][2]);
                acc[i][3] = fma2(y2, wb.y, acc[i][3]);
            }
        }
    }

    #pragma unroll
    for (int i = 0; i < 4; i++) {
        int a = base + la0 + i;
        if (a >= NN) break;
        float4 o0, o1;
        unpack2(acc[i][0], o0.x, o0.y);
        unpack2(acc[i][1], o0.z, o0.w);
        unpack2(acc[i][2], o1.x, o1.y);
        unpack2(acc[i][3], o1.z, o1.w);
        float* xo = g_x + (size_t)a * FF + f0;
        *(float4*)(xo)     = o0;
        *(float4*)(xo + 4) = o1;
    }
}

// ---------------------------------------------------------------------------
// Edge body (R13 structure, measured 341us standalone)
// ---------------------------------------------------------------------------
__device__ __forceinline__ void edge_body(
    char* dsm, int blk, const float* __restrict__ nbr_fea)
{
    const int t    = threadIdx.x;
    const int w    = t >> 5;
    const int l    = t & 31;
    const size_t base = (size_t)blk * EPB;
    uint32_t sb = smem_u32(dsm);

    float* b1_s = (float*)(dsm + OFF_B1);
    float* w2_s = b1_s + 144;
    float* b2_s = b1_s + 288;

    const float* eg = nbr_fea + base * NBR;
    float ev[NBR];
    #pragma unroll
    for (int i = 0; i < NBR; i++) ev[i] = __ldg(&eg[t + i * ETHR]);

    {
        const float4* wp4 = (const float4*)g_w1pack;
        float4* bd4 = (float4*)(dsm + OFF_B);
        #pragma unroll
        for (int i = 0; i < 2016 / ETHR + 1; i++) {
            int idx = t + i * ETHR;
            if (idx < 2016) bd4[idx] = wp4[idx];
        }
        if (t < 291) b1_s[t] = g_aux[t];
    }
    {
        char* rowH = dsm + OFF_AH + t * (KSTR * 2);
        char* rowL = dsm + OFF_AL + t * (KSTR * 2);
        *(uint16_t*)(rowH + 82) = 0; *(uint32_t*)(rowH + 84) = 0; *(ull*)(rowH + 88) = 0ULL;
        *(uint16_t*)(rowL + 82) = 0; *(uint32_t*)(rowL + 84) = 0; *(ull*)(rowL + 88) = 0ULL;
    }
    #pragma unroll
    for (int i = 0; i < NBR; i++) {
        int idx = t + i * ETHR;
        int le = idx / NBR, k = idx - le * NBR;
        float v = ev[i];
        __nv_bfloat16 hb = __float2bfloat16(v);
        float vh = __bfloat162float(hb);
        __nv_bfloat16 lb = __float2bfloat16(v - vh);
        int off = le * KSTR + k;
        ((__nv_bfloat16*)(dsm + OFF_AH))[off] = hb;
        ((__nv_bfloat16*)(dsm + OFF_AL))[off] = lb;
    }
    __syncthreads();

    const int row_sel = (l & 7) | (((l >> 3) & 1) << 3);
    const uint32_t a_lane = (uint32_t)((32 * w + row_sel) * (KSTR * 2) + (l >> 4) * 16);
    const int bm = l >> 3;
    const uint32_t b_lane = (uint32_t)(((l & 7) + (bm & 2) * 4) * (KSTR * 2) + (bm & 1) * 16);

    const uint32_t aH = sb + OFF_AH, aL = sb + OFF_AL;

    #pragma unroll 1
    for (int lay = 0; lay < NC; lay++) {
        float d[2][6][4];
        #pragma unroll
        for (int mt = 0; mt < 2; mt++)
            #pragma unroll
            for (int nt = 0; nt < 6; nt++)
                #pragma unroll
                for (int q = 0; q < 4; q++) d[mt][nt][q] = 0.f;

        const uint32_t bH = sb + OFF_B + (lay * 2 + 0) * BTILE;
        const uint32_t bL = sb + OFF_B + (lay * 2 + 1) * BTILE;

        #pragma unroll
        for (int s = 0; s < 3; s++) {
            const uint32_t Ab = ((s == 1) ? aL : aH) + a_lane;
            const uint32_t Bb = ((s == 2) ? bL : bH) + b_lane;
            #pragma unroll
            for (int k16 = 0; k16 < 3; k16++) {
                uint32_t afr[2][4];
                ldmat4(afr[0], Ab + k16 * 32);
                ldmat4(afr[1], Ab + k16 * 32 + 16 * (KSTR * 2));
                #pragma unroll
                for (int np = 0; np < 3; np++) {
                    uint32_t bfr[4];
                    ldmat4(bfr, Bb + np * (16 * KSTR * 2) + k16 * 32);
                    mma16816(d[0][2 * np],     afr[0], bfr[0], bfr[1]);
                    mma16816(d[1][2 * np],     afr[1], bfr[0], bfr[1]);
                    mma16816(d[0][2 * np + 1], afr[0], bfr[2], bfr[3]);
                    mma16816(d[1][2 * np + 1], afr[1], bfr[2], bfr[3]);
                }
            }
        }

        const float* b1l = b1_s + lay * 48;
        const float* w2l = w2_s + lay * 48;
        float b2v = b2_s[lay];
        #pragma unroll
        for (int mt = 0; mt < 2; mt++) {
            float s1 = 0.f, s2 = 0.f;
            #pragma unroll
            for (int nt = 0; nt < 5; nt++) {
                int c0 = 8 * nt + 2 * (l & 3);
                float wa = w2l[c0], wb = w2l[c0 + 1];
                float ba = b1l[c0], bb = b1l[c0 + 1];
                s1 += softplusf(d[mt][nt][0] + ba) * wa + softplusf(d[mt][nt][1] + bb) * wb;
                s2 += softplusf(d[mt][nt][2] + ba) * wa + softplusf(d[mt][nt][3] + bb) * wb;
            }
            {
                int c0 = 40 + 2 * (l & 3);
                float wa = w2l[c0], ba = b1l[c0];
                s1 += softplusf(d[mt][5][0] + ba) * wa;
                s2 += softplusf(d[mt][5][2] + ba) * wa;
            }
            s1 += __shfl_xor_sync(0xffffffffu, s1, 1);
            s1 += __shfl_xor_sync(0xffffffffu, s1, 2);
            s2 += __shfl_xor_sync(0xffffffffu, s2, 1);
            s2 += __shfl_xor_sync(0xffffffffu, s2, 2);
            if ((l & 3) == 0) {
                int r = 32 * w + 16 * mt + (l >> 2);
                g_w[(size_t)lay * NM + base + r]     = (b2v + s1) * WSCALE;
                g_w[(size_t)lay * NM + base + r + 8] = (b2v + s2) * WSCALE;
            }
        }
    }
}

// ---------------------------------------------------------------------------
// 1+2 fused: interleaved edge/embed blocks (every 7th block = embed) so the
//    tensor/issue-bound edge and fma/L1-bound embed co-reside on each SM.
//    grid = 1563*7 = 10941: embed blocks = q (r==3), edge = q*6 + adj(r).
// ---------------------------------------------------------------------------
__global__ __launch_bounds__(256, 2) void fused_kernel(
    const float* __restrict__ nbr_fea,
    const float* __restrict__ af, const float* __restrict__ W_emb,
    const float* __restrict__ b_emb)
{
    extern __shared__ char dsm[];
    int bid = blockIdx.x;
    int q = bid / 7, r = bid - q * 7;
    if (r == 3) {
        embed_body(dsm, q, af, W_emb, b_emb);
    } else {
        int eidx = q * 6 + (r < 3 ? r : r - 1);
        if (eidx < EBLK) edge_body(dsm, eidx, nbr_fea);
    }
}

// ---------------------------------------------------------------------------
// 3) Fused conv layer (unchanged R15 — 105us/layer measured)
// ---------------------------------------------------------------------------
__global__ __launch_bounds__(256, 3) void conv_kernel(
    const int* __restrict__ nbr_idx, const float* __restrict__ Wtp_l,
    const float* __restrict__ wl,
    const float* __restrict__ xin, float* __restrict__ xout)
{
    __shared__ float y_s[APB][68];
    __shared__ float sW[FF][FF];

    int t = threadIdx.x;
    for (int i = t; i < FF * FF; i += 256) sW[i >> 6][i & 63] = Wtp_l[i];

    int base = blockIdx.x * APB;

    {
        int f4 = (t & 15) * 4;
        #pragma unroll 1
        for (int pass = 0; pass < 8; pass++) {
            int la = (t >> 4) + pass * 16;
            int a  = base + la;
            float4 acc = make_float4(0.f, 0.f, 0.f, 0.f);
            if (a < NN) {
                int4   iv[3];
                float4 wv[3];
                #pragma unroll
                for (int q = 0; q < 3; q++) {
                    iv[q] = __ldg((const int4*)&nbr_idx[a * MM + q * 4]);
                    wv[q] = __ldg((const float4*)&wl[a * MM + q * 4]);
                }
                int   si[MM] = {iv[0].x, iv[0].y, iv[0].z, iv[0].w,
                                iv[1].x, iv[1].y, iv[1].z, iv[1].w,
                                iv[2].x, iv[2].y, iv[2].z, iv[2].w};
                float wj[MM] = {wv[0].x, wv[0].y, wv[0].z, wv[0].w,
                                wv[1].x, wv[1].y, wv[1].z, wv[1].w,
                                wv[2].x, wv[2].y, wv[2].z, wv[2].w};
                #pragma unroll
                for (int c = 0; c < 3; c++) {
                    float4 v[4];
                    #pragma unroll
                    for (int j = 0; j < 4; j++)
                        v[j] = __ldg((const float4*)(xin + (size_t)si[c * 4 + j] * FF + f4));
                    #pragma unroll
                    for (int j = 0; j < 4; j++) {
                        float ww = wj[c * 4 + j];
                        acc.x += ww * v[j].x; acc.y += ww * v[j].y;
                        acc.z += ww * v[j].z; acc.w += ww * v[j].w;
                    }
                }
            }
            *(float4*)&y_s[la][f4] = acc;
        }
    }
    __syncthreads();

    int fg = t & 7;
    int f0 = fg * 8;
    int la0 = (t >> 3) * 4;
    ull acc[4][4];
    #pragma unroll
    for (int i = 0; i < 4; i++)
        #pragma unroll
        for (int p = 0; p < 4; p++) acc[i][p] = 0ULL;

    #pragma unroll 4
    for (int k4 = 0; k4 < FF / 4; k4++) {
        float4 yv[4];
        #pragma unroll
        for (int i = 0; i < 4; i++) yv[i] = *(const float4*)&y_s[la0 + i][k4 * 4];
        #pragma unroll
        for (int c = 0; c < 4; c++) {
            int k = k4 * 4 + c;
            ulonglong2 wa = *(const ulonglong2*)&sW[k][f0];
            ulonglong2 wb = *(const ulonglong2*)&sW[k][f0 + 4];
            #pragma unroll
            for (int i = 0; i < 4; i++) {
                float yc = (c == 0) ? yv[i].x : (c == 1) ? yv[i].y : (c == 2) ? yv[i].z : yv[i].w;
                ull y2 = pack2(yc, yc);
                acc[i][0] = fma2(y2, wa.x, acc[i][0]);
                acc[i][1] = fma2(y2, wa.y, acc[i][1]);
                acc[i][2] = fma2(y2, wb.x, acc[i][2]);
                acc[i][3] = fma2(y2, wb.y, acc[i][3]);
            }
        }
    }

    #pragma unroll
    for (int i = 0; i < 4; i++) {
        int a = base + la0 + i;
        if (a >= NN) break;
        float4 o0, o1;
        unpack2(acc[i][0], o0.x, o0.y);
        unpack2(acc[i][1], o0.z, o0.w);
        unpack2(acc[i][2], o1.x, o1.y);
        unpack2(acc[i][3], o1.z, o1.w);
        float* xo = xout + (size_t)a * FF + f0;
        *(float4*)(xo)     = o0;
        *(float4*)(xo + 4) = o1;
    }
}

// ---------------------------------------------------------------------------
// 4) crystal pooling + fc + out (unchanged)
// ---------------------------------------------------------------------------
__global__ __launch_bounds__(128) void pool_kernel(
    const float* __restrict__ xin,
    const int* __restrict__ cidx,
    const float* __restrict__ Wfc, const float* __restrict__ bfc,
    const float* __restrict__ Wout, const float* __restrict__ bout,
    float* __restrict__ out, float* __restrict__ hout)
{
    __shared__ float scrys[FF];
    __shared__ float sred[HF];
    int b    = blockIdx.x;
    int tid  = threadIdx.x;
    int f    = tid & 63;
    int half = tid >> 6;

    float acc = 0.f;
    for (int a = half * (NPB / 2); a < (half + 1) * (NPB / 2); a++) {
        int atom = __ldg(&cidx[b * NPB + a]);
        acc += xin[(size_t)atom * FF + f];
    }
    if (half == 1) scrys[f] = acc;
    __syncthreads();
    if (half == 0) scrys[f] = (scrys[f] + acc) * (1.0f / NPB);
    __syncthreads();

    float hv = bfc[tid];
    #pragma unroll
    for (int k = 0; k < FF; k++) hv += scrys[k] * Wfc[k * HF + tid];
    hv = fmaxf(hv, 0.0f) + log1pf(__expf(-fabsf(hv)));
    if (hout) hout[(size_t)b * HF + tid] = hv;

    sred[tid] = hv * Wout[tid];
    __syncthreads();
    #pragma unroll
    for (int s = 64; s > 0; s >>= 1) {
        if (tid < s) sred[tid] += sred[tid + s];
        __syncthreads();
    }
    if (tid == 0) out[b] = sred[0] + bout[0];
}

// ---------------------------------------------------------------------------
extern "C" void kernel_launch(void* const* d_in, const int* in_sizes, int n_in,
                              void* d_out, int out_size)
{
    const float* atom_fea = (const float*)d_in[0];
    const float* nbr_fea  = (const float*)d_in[1];
    const int*   nbr_idx  = (const int*)  d_in[2];
    const int*   cidx     = (const int*)  d_in[3];
    // d_in[4] = pos : unused (Y0 is a constant)
    const float* W_emb = (const float*)d_in[5];
    const float* b_emb = (const float*)d_in[6];
    const float* Wr1   = (const float*)d_in[7];
    const float* br1   = (const float*)d_in[8];
    const float* Wr2   = (const float*)d_in[9];
    const float* br2   = (const float*)d_in[10];
    const float* Wtp   = (const float*)d_in[11];
    const float* W_fc  = (const float*)d_in[12];
    const float* b_fc  = (const float*)d_in[13];
    const float* W_out = (const float*)d_in[14];
    const float* b_out = (const float*)d_in[15];

    float* out_f = (float*)d_out;
    float* h_f   = (out_size >= BB + BB * HF) ? out_f + BB : nullptr;

    float* gx; cudaGetSymbolAddress((void**)&gx, g_x);
    float* gy; cudaGetSymbolAddress((void**)&gy, g_y);
    float* gw; cudaGetSymbolAddress((void**)&gw, g_w);

    static int smem_set = 0;
    if (!smem_set) {
        cudaFuncSetAttribute(fused_kernel,
                             cudaFuncAttributeMaxDynamicSharedMemorySize, E_SMEM);
        smem_set = 1;
    }

    // launches: [2 hidden] prep1, prep2, prep3, fused(slot 6 = ncu capture), conv x3, pool
    prep_kernel<<<2, 256>>>(Wr1, br1, Wr2, br2, 0);
    prep_kernel<<<2, 256>>>(Wr1, br1, Wr2, br2, 2);
    prep_kernel<<<2, 256>>>(Wr1, br1, Wr2, br2, 4);

    fused_kernel<<<1563 * 7, 256, E_SMEM>>>(nbr_fea, atom_fea, W_emb, b_emb);

    // layer ping-pong: x -> y -> x -> y
    conv_kernel<<<(NN + APB - 1) / APB, 256>>>(nbr_idx, Wtp + 0 * FF * FF, gw + 0 * (size_t)NM, gx, gy);
    conv_kernel<<<(NN + APB - 1) / APB, 256>>>(nbr_idx, Wtp + 1 * FF * FF, gw + 1 * (size_t)NM, gy, gx);
    conv_kernel<<<(NN + APB - 1) / APB, 256>>>(nbr_idx, Wtp + 2 * FF * FF, gw + 2 * (size_t)NM, gx, gy);

    pool_kernel<<<BB, 128>>>(gy, cidx, W_fc, b_fc, W_out, b_out, out_f, h_f);
}

// round 17
// speedup vs baseline: 1.0096x; 1.0096x over previous
#include <cuda_runtime.h>
#include <cuda_bf16.h>
#include <math.h>
#include <stdint.h>

#define NN   200000
#define MM   12
#define FF   64
#define NBR  41
#define ORIG 92
#define BB   2000
#define SHH  9
#define NC   3
#define HF   128
#define NM   (NN*MM)
#define NPB  (NN/BB)      // 100 atoms per crystal
#define APB  128          // atoms per conv/embed block
// embed kernel smem (floats): a_s [128][100] + sW [92][64] + sb [64]
#define ASTR    100
#define EMB_AS  (APB*ASTR)
#define EMB_SW  (EMB_AS + ORIG*FF)
#define EMB_SMEM ((EMB_SW + FF) * 4)      // 75008 B
// edge kernel geometry (mma.sync, 128-edge blocks, 3 blocks/SM)
#define EPB   128
#define ETHR  256
#define EBLK  18750       // NM/EPB
#define KSTR  56          // bf16 row stride (112 B)
#define OFF_AH   0        // 128*112 = 14336
#define OFF_AL   14336
#define OFF_B    28672    // 6 tiles x 5376 = 32256
#define OFF_B1   60928    // 291 floats: b1[144], w2[144], b2[3]
#define E_SMEM   62096
#define BTILE    5376
#define ETOT     (EPB*NBR)   // 5248 e floats per block
// folded: c0 * alpha * (1/M)
#define WSCALE (0.28209479177387814f * 0.125f / 12.0f)

typedef unsigned long long ull;

// scratch (allocation-free rule: __device__ globals)
__device__ float g_x[(size_t)NN * FF];
__device__ float g_y[(size_t)NN * FF];
__device__ float g_w[(size_t)NC * NM];
// prepacked edge-MLP weights (written by prep_kernel each launch)
__device__ __align__(16) __nv_bfloat16 g_w1pack[6 * 48 * KSTR];  // 32256 B
__device__ float g_aux[291];   // b1[3][48] | w2[3][48] | b2[3]

__device__ __forceinline__ float softplusf(float t) {
    return fmaxf(t, 0.0f) + __logf(1.0f + __expf(-fabsf(t)));
}

__device__ __forceinline__ ull pack2(float lo, float hi) {
    ull r; asm("mov.b64 %0, {%1, %2};" : "=l"(r) : "f"(lo), "f"(hi)); return r;
}
__device__ __forceinline__ void unpack2(ull v, float& lo, float& hi) {
    asm("mov.b64 {%0, %1}, %2;" : "=f"(lo), "=f"(hi) : "l"(v));
}
__device__ __forceinline__ ull fma2(ull a, ull b, ull c) {
    ull d; asm("fma.rn.f32x2 %0, %1, %2, %3;" : "=l"(d) : "l"(a), "l"(b), "l"(c));
    return d;
}
__device__ __forceinline__ uint32_t smem_u32(const void* p) {
    uint32_t a;
    asm("{ .reg .u64 t; cvta.to.shared.u64 t, %1; cvt.u32.u64 %0, t; }" : "=r"(a) : "l"(p));
    return a;
}
__device__ __forceinline__ void mma16816(float* d, const uint32_t* a,
                                         uint32_t b0, uint32_t b1) {
    asm volatile(
        "mma.sync.aligned.m16n8k16.row.col.f32.bf16.bf16.f32 "
        "{%0,%1,%2,%3}, {%4,%5,%6,%7}, {%8,%9}, {%0,%1,%2,%3};"
        : "+f"(d[0]), "+f"(d[1]), "+f"(d[2]), "+f"(d[3])
        : "r"(a[0]), "r"(a[1]), "r"(a[2]), "r"(a[3]), "r"(b0), "r"(b1));
}
__device__ __forceinline__ void ldmat4(uint32_t* a, uint32_t addr) {
    asm volatile("ldmatrix.sync.aligned.m8n8.x4.shared.b16 {%0,%1,%2,%3}, [%4];"
                 : "=r"(a[0]), "=r"(a[1]), "=r"(a[2]), "=r"(a[3]) : "r"(addr));
}

// ---------------------------------------------------------------------------
// 0) prep: pack W1 bf16 split tiles + aux (R13, split into 2 launches)
// ---------------------------------------------------------------------------
__global__ __launch_bounds__(256) void prep_kernel(
    const float* __restrict__ Wr1, const float* __restrict__ br1,
    const float* __restrict__ Wr2, const float* __restrict__ br2, int bofs)
{
    int b = bofs + blockIdx.x, t = threadIdx.x;
    int lay = b >> 1, split = b & 1;
    for (int i = t; i < 48 * KSTR; i += 256) {
        int r = i / KSTR, k = i - r * KSTR;
        float v = (r < NBR && k < NBR) ? __ldg(&Wr1[lay * NBR * NBR + k * NBR + r]) : 0.f;
        __nv_bfloat16 hb = __float2bfloat16(v);
        g_w1pack[b * 48 * KSTR + i] =
            split ? __float2bfloat16(v - __bfloat162float(hb)) : hb;
    }
    if (b == 0) {
        if (t < 144) {
            int l2 = t / 48, j = t - l2 * 48;
            g_aux[t] = (j < NBR) ? __ldg(&br1[l2 * NBR + j]) : 0.f;
        } else if (t < 288) {
            int q = t - 144; int l2 = q / 48, j = q - l2 * 48;
            g_aux[t] = (j < NBR) ? __ldg(&Wr2[((size_t)l2 * NBR + j) * SHH]) : 0.f;
        } else if (t < 291) {
            g_aux[t] = __ldg(&br2[(t - 288) * SHH]);
        }
    }
}

// ---------------------------------------------------------------------------
// 1) x = atom_fea @ W_emb + b_emb (R11/R15, unchanged)
// ---------------------------------------------------------------------------
__global__ __launch_bounds__(256) void embed_kernel(
    const float* __restrict__ af, const float* __restrict__ W,
    const float* __restrict__ b)
{
    extern __shared__ float sm[];
    float* a_s = sm;
    float* sW  = sm + EMB_AS;
    float* sb  = sm + EMB_SW;

    int t = threadIdx.x;
    for (int i = t; i < ORIG * FF; i += 256) sW[i] = __ldg(&W[i]);
    if (t < FF) sb[t] = __ldg(&b[t]);

    int base = blockIdx.x * APB;

    for (int idx = t; idx < APB * ORIG; idx += 256) {
        int row = idx / ORIG, col = idx - row * ORIG;
        int a = base + row;
        a_s[row * ASTR + col] = (a < NN) ? __ldg(&af[(size_t)a * ORIG + col]) : 0.f;
    }
    __syncthreads();

    int la0 = (t >> 3) * 4;
    int f0  = (t & 7) * 8;
    ull acc[4][4];
    {
        ull b0 = pack2(sb[f0],     sb[f0 + 1]);
        ull b1 = pack2(sb[f0 + 2], sb[f0 + 3]);
        ull b2 = pack2(sb[f0 + 4], sb[f0 + 5]);
        ull b3 = pack2(sb[f0 + 6], sb[f0 + 7]);
        #pragma unroll
        for (int i = 0; i < 4; i++) {
            acc[i][0] = b0; acc[i][1] = b1; acc[i][2] = b2; acc[i][3] = b3;
        }
    }

    #pragma unroll 4
    for (int k4 = 0; k4 < ORIG / 4; k4++) {
        float4 yv[4];
        #pragma unroll
        for (int i = 0; i < 4; i++)
            yv[i] = *(const float4*)&a_s[(la0 + i) * ASTR + k4 * 4];
        #pragma unroll
        for (int c = 0; c < 4; c++) {
            int k = k4 * 4 + c;
            ulonglong2 wa = *(const ulonglong2*)&sW[k * FF + f0];
            ulonglong2 wb = *(const ulonglong2*)&sW[k * FF + f0 + 4];
            #pragma unroll
            for (int i = 0; i < 4; i++) {
                float yc = (c == 0) ? yv[i].x : (c == 1) ? yv[i].y : (c == 2) ? yv[i].z : yv[i].w;
                ull y2 = pack2(yc, yc);
                acc[i][0] = fma2(y2, wa.x, acc[i][0]);
                acc[i][1] = fma2(y2, wa.y, acc[i][1]);
                acc[i][2] = fma2(y2, wb.x, acc[i][2]);
                acc[i][3] = fma2(y2, wb.y, acc[i][3]);
            }
        }
    }

    #pragma unroll
    for (int i = 0; i < 4; i++) {
        int a = base + la0 + i;
        if (a >= NN) break;
        float4 o0, o1;
        unpack2(acc[i][0], o0.x, o0.y);
        unpack2(acc[i][1], o0.z, o0.w);
        unpack2(acc[i][2], o1.x, o1.y);
        unpack2(acc[i][3], o1.z, o1.w);
        float* xo = g_x + (size_t)a * FF + f0;
        *(float4*)(xo)     = o0;
        *(float4*)(xo + 4) = o1;
    }
}

// ---------------------------------------------------------------------------
// 2) Edge radial scalars — 128 edges/block, 8 warps (1 m16-tile each),
//    62.1 KB smem -> 3 blocks/SM (24 warps).
// ---------------------------------------------------------------------------
__global__ __launch_bounds__(ETHR, 3) void edge_kernel(const float* __restrict__ nbr_fea)
{
    extern __shared__ char dsm[];
    const int t    = threadIdx.x;
    const int w    = t >> 5;
    const int l    = t & 31;
    const size_t base = (size_t)blockIdx.x * EPB;
    uint32_t sb = smem_u32(dsm);

    float* b1_s = (float*)(dsm + OFF_B1);
    float* w2_s = b1_s + 144;
    float* b2_s = b1_s + 288;

    // front-batched e loads (ETOT = 5248 floats; 21 per thread, guarded)
    const float* eg = nbr_fea + base * NBR;
    float ev[21];
    #pragma unroll
    for (int i = 0; i < 21; i++) {
        int idx = t + i * ETHR;
        ev[i] = (idx < ETOT) ? __ldg(&eg[idx]) : 0.f;
    }

    // copy prepacked B tiles + aux
    {
        const float4* wp4 = (const float4*)g_w1pack;
        float4* bd4 = (float4*)(dsm + OFF_B);
        #pragma unroll
        for (int i = 0; i < 8; i++) {
            int idx = t + i * ETHR;
            if (idx < 2016) bd4[idx] = wp4[idx];
        }
        if (t < 291) b1_s[t] = g_aux[t];
    }
    // zero A pad cols 41..47 (bytes 82..96), rows 0..127
    if (t < EPB) {
        char* rowH = dsm + OFF_AH + t * (KSTR * 2);
        char* rowL = dsm + OFF_AL + t * (KSTR * 2);
        *(uint16_t*)(rowH + 82) = 0; *(uint32_t*)(rowH + 84) = 0; *(ull*)(rowH + 88) = 0ULL;
        *(uint16_t*)(rowL + 82) = 0; *(uint32_t*)(rowL + 84) = 0; *(ull*)(rowL + 88) = 0ULL;
    }
    // convert e splits into A tiles (cols 0..40)
    #pragma unroll
    for (int i = 0; i < 21; i++) {
        int idx = t + i * ETHR;
        if (idx < ETOT) {
            int le = idx / NBR, k = idx - le * NBR;
            float v = ev[i];
            __nv_bfloat16 hb = __float2bfloat16(v);
            float vh = __bfloat162float(hb);
            __nv_bfloat16 lb = __float2bfloat16(v - vh);
            int off = le * KSTR + k;
            ((__nv_bfloat16*)(dsm + OFF_AH))[off] = hb;
            ((__nv_bfloat16*)(dsm + OFF_AL))[off] = lb;
        }
    }
    __syncthreads();

    // A-ldmatrix lane mapping: warp w owns rows 16w..16w+15
    const int row_sel = (l & 7) | (((l >> 3) & 1) << 3);
    const uint32_t a_lane = (uint32_t)((16 * w + row_sel) * (KSTR * 2) + (l >> 4) * 16);
    // B-ldmatrix lane mapping (two n-tiles per x4)
    const int bm = l >> 3;
    const uint32_t b_lane = (uint32_t)(((l & 7) + (bm & 2) * 4) * (KSTR * 2) + (bm & 1) * 16);

    const uint32_t aH = sb + OFF_AH, aL = sb + OFF_AL;

    #pragma unroll 1
    for (int lay = 0; lay < NC; lay++) {
        float d[6][4];
        #pragma unroll
        for (int nt = 0; nt < 6; nt++)
            #pragma unroll
            for (int q = 0; q < 4; q++) d[nt][q] = 0.f;

        const uint32_t bH = sb + OFF_B + (lay * 2 + 0) * BTILE;
        const uint32_t bL = sb + OFF_B + (lay * 2 + 1) * BTILE;

        #pragma unroll
        for (int s = 0; s < 3; s++) {
            const uint32_t Ab = ((s == 1) ? aL : aH) + a_lane;   // s0:AhBh s1:AlBh s2:AhBl
            const uint32_t Bb = ((s == 2) ? bL : bH) + b_lane;
            #pragma unroll
            for (int k16 = 0; k16 < 3; k16++) {
                uint32_t afr[4];
                ldmat4(afr, Ab + k16 * 32);
                #pragma unroll
                for (int np = 0; np < 3; np++) {
                    uint32_t bfr[4];
                    ldmat4(bfr, Bb + np * (16 * KSTR * 2) + k16 * 32);
                    mma16816(d[2 * np],     afr, bfr[0], bfr[1]);
                    mma16816(d[2 * np + 1], afr, bfr[2], bfr[3]);
                }
            }
        }

        // ---- epilogue: rows r = 16w + (l>>2), r+8; cols 8nt+2(l&3), +1 ----
        const float* b1l = b1_s + lay * 48;
        const float* w2l = w2_s + lay * 48;
        float b2v = b2_s[lay];
        float s1 = 0.f, s2 = 0.f;
        #pragma unroll
        for (int nt = 0; nt < 5; nt++) {
            int c0 = 8 * nt + 2 * (l & 3);
            float wa = w2l[c0], wb = w2l[c0 + 1];
            float ba = b1l[c0], bb = b1l[c0 + 1];
            s1 += softplusf(d[nt][0] + ba) * wa + softplusf(d[nt][1] + bb) * wb;
            s2 += softplusf(d[nt][2] + ba) * wa + softplusf(d[nt][3] + bb) * wb;
        }
        {   // nt = 5: only col 40 has nonzero w2
            int c0 = 40 + 2 * (l & 3);
            float wa = w2l[c0], ba = b1l[c0];
            s1 += softplusf(d[5][0] + ba) * wa;
            s2 += softplusf(d[5][2] + ba) * wa;
        }
        s1 += __shfl_xor_sync(0xffffffffu, s1, 1);
        s1 += __shfl_xor_sync(0xffffffffu, s1, 2);
        s2 += __shfl_xor_sync(0xffffffffu, s2, 1);
        s2 += __shfl_xor_sync(0xffffffffu, s2, 2);
        if ((l & 3) == 0) {
            int r = 16 * w + (l >> 2);
            g_w[(size_t)lay * NM + base + r]     = (b2v + s1) * WSCALE;
            g_w[(size_t)lay * NM + base + r + 8] = (b2v + s2) * WSCALE;
        }
    }
}

// ---------------------------------------------------------------------------
// 3) Fused conv layer (unchanged R15 — 105us/layer measured)
// ---------------------------------------------------------------------------
__global__ __launch_bounds__(256, 3) void conv_kernel(
    const int* __restrict__ nbr_idx, const float* __restrict__ Wtp_l,
    const float* __restrict__ wl,
    const float* __restrict__ xin, float* __restrict__ xout)
{
    __shared__ float y_s[APB][68];
    __shared__ float sW[FF][FF];

    int t = threadIdx.x;
    for (int i = t; i < FF * FF; i += 256) sW[i >> 6][i & 63] = Wtp_l[i];

    int base = blockIdx.x * APB;

    {
        int f4 = (t & 15) * 4;
        #pragma unroll 1
        for (int pass = 0; pass < 8; pass++) {
            int la = (t >> 4) + pass * 16;
            int a  = base + la;
            float4 acc = make_float4(0.f, 0.f, 0.f, 0.f);
            if (a < NN) {
                int4   iv[3];
                float4 wv[3];
                #pragma unroll
                for (int q = 0; q < 3; q++) {
                    iv[q] = __ldg((const int4*)&nbr_idx[a * MM + q * 4]);
                    wv[q] = __ldg((const float4*)&wl[a * MM + q * 4]);
                }
                int   si[MM] = {iv[0].x, iv[0].y, iv[0].z, iv[0].w,
                                iv[1].x, iv[1].y, iv[1].z, iv[1].w,
                                iv[2].x, iv[2].y, iv[2].z, iv[2].w};
                float wj[MM] = {wv[0].x, wv[0].y, wv[0].z, wv[0].w,
                                wv[1].x, wv[1].y, wv[1].z, wv[1].w,
                                wv[2].x, wv[2].y, wv[2].z, wv[2].w};
                #pragma unroll
                for (int c = 0; c < 3; c++) {
                    float4 v[4];
                    #pragma unroll
                    for (int j = 0; j < 4; j++)
                        v[j] = __ldg((const float4*)(xin + (size_t)si[c * 4 + j] * FF + f4));
                    #pragma unroll
                    for (int j = 0; j < 4; j++) {
                        float ww = wj[c * 4 + j];
                        acc.x += ww * v[j].x; acc.y += ww * v[j].y;
                        acc.z += ww * v[j].z; acc.w += ww * v[j].w;
                    }
                }
            }
            *(float4*)&y_s[la][f4] = acc;
        }
    }
    __syncthreads();

    int fg = t & 7;
    int f0 = fg * 8;
    int la0 = (t >> 3) * 4;
    ull acc[4][4];
    #pragma unroll
    for (int i = 0; i < 4; i++)
        #pragma unroll
        for (int p = 0; p < 4; p++) acc[i][p] = 0ULL;

    #pragma unroll 4
    for (int k4 = 0; k4 < FF / 4; k4++) {
        float4 yv[4];
        #pragma unroll
        for (int i = 0; i < 4; i++) yv[i] = *(const float4*)&y_s[la0 + i][k4 * 4];
        #pragma unroll
        for (int c = 0; c < 4; c++) {
            int k = k4 * 4 + c;
            ulonglong2 wa = *(const ulonglong2*)&sW[k][f0];
            ulonglong2 wb = *(const ulonglong2*)&sW[k][f0 + 4];
            #pragma unroll
            for (int i = 0; i < 4; i++) {
                float yc = (c == 0) ? yv[i].x : (c == 1) ? yv[i].y : (c == 2) ? yv[i].z : yv[i].w;
                ull y2 = pack2(yc, yc);
                acc[i][0] = fma2(y2, wa.x, acc[i][0]);
                acc[i][1] = fma2(y2, wa.y, acc[i][1]);
                acc[i][2] = fma2(y2, wb.x, acc[i][2]);
                acc[i][3] = fma2(y2, wb.y, acc[i][3]);
            }
        }
    }

    #pragma unroll
    for (int i = 0; i < 4; i++) {
        int a = base + la0 + i;
        if (a >= NN) break;
        float4 o0, o1;
        unpack2(acc[i][0], o0.x, o0.y);
        unpack2(acc[i][1], o0.z, o0.w);
        unpack2(acc[i][2], o1.x, o1.y);
        unpack2(acc[i][3], o1.z, o1.w);
        float* xo = xout + (size_t)a * FF + f0;
        *(float4*)(xo)     = o0;
        *(float4*)(xo + 4) = o1;
    }
}

// ---------------------------------------------------------------------------
// 4) crystal pooling + fc + out (unchanged)
// ---------------------------------------------------------------------------
__global__ __launch_bounds__(128) void pool_kernel(
    const float* __restrict__ xin,
    const int* __restrict__ cidx,
    const float* __restrict__ Wfc, const float* __restrict__ bfc,
    const float* __restrict__ Wout, const float* __restrict__ bout,
    float* __restrict__ out, float* __restrict__ hout)
{
    __shared__ float scrys[FF];
    __shared__ float sred[HF];
    int b    = blockIdx.x;
    int tid  = threadIdx.x;
    int f    = tid & 63;
    int half = tid >> 6;

    float acc = 0.f;
    for (int a = half * (NPB / 2); a < (half + 1) * (NPB / 2); a++) {
        int atom = __ldg(&cidx[b * NPB + a]);
        acc += xin[(size_t)atom * FF + f];
    }
    if (half == 1) scrys[f] = acc;
    __syncthreads();
    if (half == 0) scrys[f] = (scrys[f] + acc) * (1.0f / NPB);
    __syncthreads();

    float hv = bfc[tid];
    #pragma unroll
    for (int k = 0; k < FF; k++) hv += scrys[k] * Wfc[k * HF + tid];
    hv = fmaxf(hv, 0.0f) + log1pf(__expf(-fabsf(hv)));
    if (hout) hout[(size_t)b * HF + tid] = hv;

    sred[tid] = hv * Wout[tid];
    __syncthreads();
    #pragma unroll
    for (int s = 64; s > 0; s >>= 1) {
        if (tid < s) sred[tid] += sred[tid + s];
        __syncthreads();
    }
    if (tid == 0) out[b] = sred[0] + bout[0];
}

// ---------------------------------------------------------------------------
extern "C" void kernel_launch(void* const* d_in, const int* in_sizes, int n_in,
                              void* d_out, int out_size)
{
    const float* atom_fea = (const float*)d_in[0];
    const float* nbr_fea  = (const float*)d_in[1];
    const int*   nbr_idx  = (const int*)  d_in[2];
    const int*   cidx     = (const int*)  d_in[3];
    // d_in[4] = pos : unused (Y0 is a constant)
    const float* W_emb = (const float*)d_in[5];
    const float* b_emb = (const float*)d_in[6];
    const float* Wr1   = (const float*)d_in[7];
    const float* br1   = (const float*)d_in[8];
    const float* Wr2   = (const float*)d_in[9];
    const float* br2   = (const float*)d_in[10];
    const float* Wtp   = (const float*)d_in[11];
    const float* W_fc  = (const float*)d_in[12];
    const float* b_fc  = (const float*)d_in[13];
    const float* W_out = (const float*)d_in[14];
    const float* b_out = (const float*)d_in[15];

    float* out_f = (float*)d_out;
    float* h_f   = (out_size >= BB + BB * HF) ? out_f + BB : nullptr;

    float* gx; cudaGetSymbolAddress((void**)&gx, g_x);
    float* gy; cudaGetSymbolAddress((void**)&gy, g_y);
    float* gw; cudaGetSymbolAddress((void**)&gw, g_w);

    static int smem_set = 0;
    if (!smem_set) {
        cudaFuncSetAttribute(edge_kernel,
                             cudaFuncAttributeMaxDynamicSharedMemorySize, E_SMEM);
        cudaFuncSetAttribute(embed_kernel,
                             cudaFuncAttributeMaxDynamicSharedMemorySize, EMB_SMEM);
        smem_set = 1;
    }

    // launches: [2 hidden] prep1, prep2, embed, edge(slot 6 = ncu capture), conv x3, pool
    prep_kernel<<<3, 256>>>(Wr1, br1, Wr2, br2, 0);
    prep_kernel<<<3, 256>>>(Wr1, br1, Wr2, br2, 3);
    embed_kernel<<<(NN + APB - 1) / APB, 256, EMB_SMEM>>>(atom_fea, W_emb, b_emb);

    edge_kernel<<<EBLK, ETHR, E_SMEM>>>(nbr_fea);

    // layer ping-pong: x -> y -> x -> y
    conv_kernel<<<(NN + APB - 1) / APB, 256>>>(nbr_idx, Wtp + 0 * FF * FF, gw + 0 * (size_t)NM, gx, gy);
    conv_kernel<<<(NN + APB - 1) / APB, 256>>>(nbr_idx, Wtp + 1 * FF * FF, gw + 1 * (size_t)NM, gy, gx);
    conv_kernel<<<(NN + APB - 1) / APB, 256>>>(nbr_idx, Wtp + 2 * FF * FF, gw + 2 * (size_t)NM, gx, gy);

    pool_kernel<<<BB, 128>>>(gy, cidx, W_fc, b_fc, W_out, b_out, out_f, h_f);
}